// round 1
// baseline (speedup 1.0000x reference)
#include <cuda_runtime.h>
#include <math.h>

#define N_NODES 10000
#define N_EDGES 160000
#define N_GRAPHS 64
#define T_TOW 5
#define FI 75              // F_IN
#define FO 15              // F_OUT
#define N_LAYERS 4
#define MSG_DIM 375        // T*FI
#define MIN_DIM 225        // 3*FI
#define OUT_DIM 975        // 13*FI
#define POST_DIM 75        // T*FO
#define AVG_DEG_LOG 2.8332133440562162f   // ln(17)

// ---------------- scratch (__device__ globals; no cudaMalloc allowed) -------
__device__ float d_h[N_NODES * FI];
__device__ float d_hc[N_NODES * FI];
__device__ float d_mfeat[N_EDGES * MIN_DIM];     // m_in  [E,225]  (144 MB)
__device__ float d_msgs[N_EDGES * MSG_DIM];      // msgs  [E,375]  (240 MB)
__device__ float d_agg[N_NODES * T_TOW * 4 * FI];// agg   [N,T,300]
__device__ float d_Wt[MIN_DIM * MSG_DIM];        // transposed pre_W[l]  [225,375]
__device__ int   d_cnt[N_NODES];
__device__ int   d_rowstart[N_NODES + 1];
__device__ int   d_cursor[N_NODES];
__device__ int   d_elist[N_EDGES];
__device__ float d_bnsum[FI];
__device__ float d_bnsq[FI];
__device__ float d_pool[N_GRAPHS * FI];

// ---------------- initial node features: h0 = emb-gather @ pre_lin_W + b ----
__global__ void k_h0(const int* __restrict__ x, const float* __restrict__ node_emb,
                     const float* __restrict__ W, const float* __restrict__ b) {
    int idx = blockIdx.x * blockDim.x + threadIdx.x;
    if (idx >= N_NODES * FI) return;
    int n = idx / FI, f = idx % FI;
    int i0 = x[n * 2 + 0], i1 = x[n * 2 + 1];
    const float* e0 = node_emb + i0 * FI;
    const float* e1 = node_emb + i1 * FI;
    float acc = b[f];
    #pragma unroll 5
    for (int c = 0; c < FI; c++) acc += e0[c] * W[c * FI + f];
    #pragma unroll 5
    for (int c = 0; c < FI; c++) acc += e1[c] * W[(FI + c) * FI + f];
    d_h[idx] = acc;
}

// ---------------- CSR build ------------------------------------------------
__global__ void k_zero_cnt() {
    int i = blockIdx.x * blockDim.x + threadIdx.x;
    if (i < N_NODES) d_cnt[i] = 0;
}

__global__ void k_count(const int* __restrict__ edge_index) {
    int e = blockIdx.x * blockDim.x + threadIdx.x;
    if (e >= N_EDGES) return;
    atomicAdd(&d_cnt[edge_index[N_EDGES + e]], 1);   // dst = row 1
}

// single-block exclusive scan over N_NODES counts (1024 threads x 10 items)
__global__ void k_scan() {
    __shared__ int ssum[1024];
    int tid = threadIdx.x;
    const int ITEMS = 10;
    int base = tid * ITEMS;
    int local[ITEMS];
    int s = 0;
    #pragma unroll
    for (int i = 0; i < ITEMS; i++) {
        int g = base + i;
        int v = (g < N_NODES) ? d_cnt[g] : 0;
        local[i] = s;
        s += v;
    }
    ssum[tid] = s;
    __syncthreads();
    // Hillis-Steele inclusive scan
    for (int off = 1; off < 1024; off <<= 1) {
        int v = (tid >= off) ? ssum[tid - off] : 0;
        __syncthreads();
        ssum[tid] += v;
        __syncthreads();
    }
    int excl = (tid == 0) ? 0 : ssum[tid - 1];
    #pragma unroll
    for (int i = 0; i < ITEMS; i++) {
        int g = base + i;
        if (g < N_NODES) {
            int rs = excl + local[i];
            d_rowstart[g] = rs;
            d_cursor[g]   = rs;
        }
    }
    if (tid == 0) d_rowstart[N_NODES] = ssum[1023];
}

__global__ void k_fill(const int* __restrict__ edge_index) {
    int e = blockIdx.x * blockDim.x + threadIdx.x;
    if (e >= N_EDGES) return;
    int dst = edge_index[N_EDGES + e];
    int pos = atomicAdd(&d_cursor[dst], 1);
    d_elist[pos] = e;
}

// ---------------- build m_in = [h[dst], h[src], edge_enc] ------------------
__global__ void k_min(const int* __restrict__ edge_index, const int* __restrict__ edge_attr,
                      const float* __restrict__ edge_emb,
                      const float* __restrict__ encW, const float* __restrict__ encb) {
    int idx = blockIdx.x * blockDim.x + threadIdx.x;
    if (idx >= N_EDGES * MIN_DIM) return;
    int e = idx / MIN_DIM, c = idx % MIN_DIM;
    float v;
    if (c < FI) {
        int dst = edge_index[N_EDGES + e];
        v = d_h[dst * FI + c];
    } else if (c < 2 * FI) {
        int src = edge_index[e];
        v = d_h[src * FI + (c - FI)];
    } else {
        int f = c - 2 * FI;
        int a0 = edge_attr[e * 2 + 0], a1 = edge_attr[e * 2 + 1];
        const float* ea0 = edge_emb + a0 * 25;
        const float* ea1 = edge_emb + a1 * 25;
        float acc = encb[f];
        #pragma unroll 5
        for (int q = 0; q < 25; q++) acc += ea0[q] * encW[q * FI + f];
        #pragma unroll 5
        for (int q = 0; q < 25; q++) acc += ea1[q] * encW[(25 + q) * FI + f];
        v = acc;
    }
    d_mfeat[idx] = v;
}

// ---------------- transpose pre_W[l] (T,225,75) -> (225,375) ----------------
__global__ void k_transpose(const float* __restrict__ preW) {
    int idx = blockIdx.x * blockDim.x + threadIdx.x;
    if (idx >= MIN_DIM * MSG_DIM) return;
    int c = idx / MSG_DIM, j = idx % MSG_DIM;
    int t = j / FI, f = j % FI;
    d_Wt[idx] = preW[(t * MIN_DIM + c) * FI + f];
}

// ---------------- msgs = m_in @ Wt + bias  (E x 225 x 375) ------------------
// 64x64 tile, BK=16, 256 threads, 4x4 per thread
__global__ void k_gemm(const float* __restrict__ bias) {
    const int BM = 64, BN = 64, BK = 16;
    __shared__ float As[BM][BK + 1];
    __shared__ float Bs[BK][BN + 1];
    int bx = blockIdx.x;     // col-block 0..5
    int by = blockIdx.y;     // row-block 0..2499
    int tid = threadIdx.x;
    int tx = tid & 15, ty = tid >> 4;
    int row0 = by * BM, col0 = bx * BN;
    float acc[4][4] = {};
    for (int k0 = 0; k0 < MIN_DIM; k0 += BK) {
        #pragma unroll
        for (int p = 0; p < 4; p++) {
            int r = (tid >> 4) + p * 16;
            int c = tid & 15;
            int kk = k0 + c;
            As[r][c] = (kk < MIN_DIM) ? d_mfeat[(row0 + r) * MIN_DIM + kk] : 0.f;
        }
        #pragma unroll
        for (int p = 0; p < 4; p++) {
            int kr = (tid >> 6) + p * 4;
            int c = tid & 63;
            int kk = k0 + kr, j = col0 + c;
            Bs[kr][c] = (kk < MIN_DIM && j < MSG_DIM) ? d_Wt[kk * MSG_DIM + j] : 0.f;
        }
        __syncthreads();
        #pragma unroll
        for (int kk = 0; kk < BK; kk++) {
            float a[4], b[4];
            #pragma unroll
            for (int i = 0; i < 4; i++) a[i] = As[ty * 4 + i][kk];
            #pragma unroll
            for (int j = 0; j < 4; j++) b[j] = Bs[kk][tx * 4 + j];
            #pragma unroll
            for (int i = 0; i < 4; i++)
                #pragma unroll
                for (int j = 0; j < 4; j++) acc[i][j] += a[i] * b[j];
        }
        __syncthreads();
    }
    #pragma unroll
    for (int i = 0; i < 4; i++) {
        int r = row0 + ty * 4 + i;
        #pragma unroll
        for (int j = 0; j < 4; j++) {
            int col = col0 + tx * 4 + j;
            if (col < MSG_DIM) d_msgs[r * MSG_DIM + col] = acc[i][j] + bias[col];
        }
    }
}

// ---------------- per-node segment reduce: mean / min / max / std -----------
__global__ void k_agg() {
    int n = blockIdx.x;
    int j = threadIdx.x;          // 384 threads, 375 active
    if (j >= MSG_DIM) return;
    int s0 = d_rowstart[n], s1 = d_rowstart[n + 1];
    float s = 0.f, sq = 0.f, mn = 3.4e38f, mx = -3.4e38f;
    for (int i = s0; i < s1; i++) {
        int e = d_elist[i];
        float v = d_msgs[e * MSG_DIM + j];
        s += v; sq += v * v;
        mn = fminf(mn, v); mx = fmaxf(mx, v);
    }
    float cnt = (float)(s1 - s0);
    float deg = fmaxf(cnt, 1.f);
    float mean = s / deg;
    float var = sq / deg - mean * mean;
    if (var < 0.f) var = 0.f;
    float stdv = sqrtf(var + 1e-5f);
    if (s1 == s0) { mn = 0.f; mx = 0.f; }
    int t = j / FI, f = j % FI;
    float* a = d_agg + n * (T_TOW * 4 * FI) + t * (4 * FI);
    a[f]          = mean;
    a[FI + f]     = mn;
    a[2 * FI + f] = mx;
    a[3 * FI + f] = stdv;
}

__global__ void k_bnzero() {
    int i = threadIdx.x;
    if (i < FI) { d_bnsum[i] = 0.f; d_bnsq[i] = 0.f; }
}

// ---------------- per-node post-tower GEMM + lin -> hc, BN stats ------------
__global__ void k_post(const float* __restrict__ postW, const float* __restrict__ postb,
                       const float* __restrict__ linW,  const float* __restrict__ linb) {
    __shared__ float outs[T_TOW * OUT_DIM];   // 4875 floats
    __shared__ float posts[POST_DIM];         // 75
    int n = blockIdx.x;
    int tid = threadIdx.x;                    // 128
    float cnt = (float)(d_rowstart[n + 1] - d_rowstart[n]);
    float log_deg = logf(fmaxf(cnt, 1.f) + 1.f);
    float amp = log_deg / AVG_DEG_LOG;
    float att = AVG_DEG_LOG / log_deg;
    const float* hrow = d_h + n * FI;
    const float* arow = d_agg + n * (T_TOW * 4 * FI);
    for (int idx = tid; idx < T_TOW * OUT_DIM; idx += 128) {
        int t = idx / OUT_DIM, c = idx % OUT_DIM;
        float v;
        if (c < FI) {
            v = hrow[c];
        } else {
            int c2 = c - FI;
            int blk = c2 / (4 * FI);          // 0: raw, 1: *amp, 2: *att
            int k = c2 % (4 * FI);
            v = arow[t * (4 * FI) + k];
            if (blk == 1) v *= amp;
            else if (blk == 2) v *= att;
        }
        outs[idx] = v;
    }
    __syncthreads();
    if (tid < POST_DIM) {
        int t = tid / FO, f = tid % FO;
        float acc = postb[t * FO + f];
        const float* w = postW + t * OUT_DIM * FO + f;
        const float* o = outs + t * OUT_DIM;
        for (int c = 0; c < OUT_DIM; c++) acc += o[c] * w[c * FO];
        posts[tid] = acc;
    }
    __syncthreads();
    if (tid < FI) {
        float acc = linb[tid];
        #pragma unroll 5
        for (int j = 0; j < POST_DIM; j++) acc += posts[j] * linW[j * FI + tid];
        d_hc[n * FI + tid] = acc;
        atomicAdd(&d_bnsum[tid], acc);
        atomicAdd(&d_bnsq[tid],  acc * acc);
    }
}

// ---------------- batchnorm (training-mode stats) + relu -> h ---------------
__global__ void k_bn(const float* __restrict__ g, const float* __restrict__ b) {
    int idx = blockIdx.x * blockDim.x + threadIdx.x;
    if (idx >= N_NODES * FI) return;
    int f = idx % FI;
    float mu = d_bnsum[f] / (float)N_NODES;
    float var = d_bnsq[f] / (float)N_NODES - mu * mu;
    float v = (d_hc[idx] - mu) * rsqrtf(var + 1e-5f) * g[f] + b[f];
    d_h[idx] = fmaxf(v, 0.f);
}

// ---------------- global add pool + MLP -------------------------------------
__global__ void k_poolzero() {
    int i = blockIdx.x * blockDim.x + threadIdx.x;
    if (i < N_GRAPHS * FI) d_pool[i] = 0.f;
}

__global__ void k_pool(const int* __restrict__ batch) {
    int idx = blockIdx.x * blockDim.x + threadIdx.x;
    if (idx >= N_NODES * FI) return;
    int n = idx / FI, f = idx % FI;
    atomicAdd(&d_pool[batch[n] * FI + f], d_h[idx]);
}

__global__ void k_mlp(const float* __restrict__ W1, const float* __restrict__ b1,
                      const float* __restrict__ W2, const float* __restrict__ b2,
                      const float* __restrict__ W3, const float* __restrict__ b3,
                      float* __restrict__ out) {
    __shared__ float g[FI], h1[50], h2[25];
    int gi = blockIdx.x;
    int tid = threadIdx.x;
    if (tid < FI) g[tid] = d_pool[gi * FI + tid];
    __syncthreads();
    if (tid < 50) {
        float a = b1[tid];
        for (int c = 0; c < FI; c++) a += g[c] * W1[c * 50 + tid];
        h1[tid] = fmaxf(a, 0.f);
    }
    __syncthreads();
    if (tid < 25) {
        float a = b2[tid];
        for (int c = 0; c < 50; c++) a += h1[c] * W2[c * 25 + tid];
        h2[tid] = fmaxf(a, 0.f);
    }
    __syncthreads();
    if (tid == 0) {
        float a = b3[0];
        for (int c = 0; c < 25; c++) a += h2[c] * W3[c];
        out[gi] = a;
    }
}

// ---------------- launch ----------------------------------------------------
extern "C" void kernel_launch(void* const* d_in, const int* in_sizes, int n_in,
                              void* d_out, int out_size) {
    const int*   x          = (const int*)d_in[0];
    const int*   edge_index = (const int*)d_in[1];
    const int*   edge_attr  = (const int*)d_in[2];
    const int*   batch      = (const int*)d_in[3];
    const float* node_emb   = (const float*)d_in[4];
    const float* edge_emb   = (const float*)d_in[5];
    const float* pre_lin_W  = (const float*)d_in[6];
    const float* pre_lin_b  = (const float*)d_in[7];
    const float* edge_enc_W = (const float*)d_in[8];   // [L,50,75]
    const float* edge_enc_b = (const float*)d_in[9];   // [L,75]
    const float* pre_W      = (const float*)d_in[10];  // [L,T,225,75]
    const float* pre_b      = (const float*)d_in[11];  // [L,T,75]
    const float* post_W     = (const float*)d_in[12];  // [L,T,975,15]
    const float* post_b     = (const float*)d_in[13];  // [L,T,15]
    const float* lin_W      = (const float*)d_in[14];  // [L,75,75]
    const float* lin_b      = (const float*)d_in[15];  // [L,75]
    const float* bn_g       = (const float*)d_in[16];
    const float* bn_b       = (const float*)d_in[17];
    const float* mlp_W1     = (const float*)d_in[18];
    const float* mlp_b1     = (const float*)d_in[19];
    const float* mlp_W2     = (const float*)d_in[20];
    const float* mlp_b2     = (const float*)d_in[21];
    const float* mlp_W3     = (const float*)d_in[22];
    const float* mlp_b3     = (const float*)d_in[23];
    float* out = (float*)d_out;

    // node features
    k_h0<<<(N_NODES * FI + 255) / 256, 256>>>(x, node_emb, pre_lin_W, pre_lin_b);

    // CSR by dst
    k_zero_cnt<<<(N_NODES + 255) / 256, 256>>>();
    k_count<<<(N_EDGES + 255) / 256, 256>>>(edge_index);
    k_scan<<<1, 1024>>>();
    k_fill<<<(N_EDGES + 255) / 256, 256>>>(edge_index);

    for (int l = 0; l < N_LAYERS; l++) {
        k_min<<<(N_EDGES * MIN_DIM + 255) / 256, 256>>>(
            edge_index, edge_attr, edge_emb,
            edge_enc_W + l * 50 * FI, edge_enc_b + l * FI);
        k_transpose<<<(MIN_DIM * MSG_DIM + 255) / 256, 256>>>(
            pre_W + (size_t)l * T_TOW * MIN_DIM * FI);
        k_bnzero<<<1, 128>>>();
        k_gemm<<<dim3((MSG_DIM + 63) / 64, N_EDGES / 64), 256>>>(pre_b + l * MSG_DIM);
        k_agg<<<N_NODES, 384>>>();
        k_post<<<N_NODES, 128>>>(post_W + (size_t)l * T_TOW * OUT_DIM * FO,
                                 post_b + l * POST_DIM,
                                 lin_W + l * POST_DIM * FI,
                                 lin_b + l * FI);
        k_bn<<<(N_NODES * FI + 255) / 256, 256>>>(bn_g + l * FI, bn_b + l * FI);
    }

    k_poolzero<<<(N_GRAPHS * FI + 255) / 256, 256>>>();
    k_pool<<<(N_NODES * FI + 255) / 256, 256>>>(batch);
    k_mlp<<<N_GRAPHS, 128>>>(mlp_W1, mlp_b1, mlp_W2, mlp_b2, mlp_W3, mlp_b3, out);
}